// round 1
// baseline (speedup 1.0000x reference)
#include <cuda_runtime.h>
#include <math.h>

#define K_DIM 1000
#define N_DIM 1000
#define M_PTS 900000
#define SENTINEL -9999.0f

// Scratch grid: packed cells. High 32 bits = (m+1) (scatter order priority,
// last-write-wins like XLA in-order scatter), low 32 bits = float bits of val.
// 0 == never written.
__device__ unsigned long long g_cells[K_DIM * N_DIM];

__global__ void init_kernel(float* out) {
    int i = blockIdx.x * blockDim.x + threadIdx.x;
    if (i < K_DIM * N_DIM) g_cells[i] = 0ull;
    if (i < N_DIM) out[K_DIM + i] = -INFINITY;  // col_max accumulators
}

// Weight shared-memory layout offsets
#define OFF_W1 0
#define OFF_B1 126
#define OFF_W2 144
#define OFF_B2 792
#define OFF_W3 828
#define OFF_B3 2124
#define OFF_W4 2160
#define OFF_B4 2196
#define W_TOTAL 2197

__global__ __launch_bounds__(256) void mlp_scatter_kernel(
    const float* __restrict__ xin, const int* __restrict__ tind,
    const float* __restrict__ w1, const float* __restrict__ b1,
    const float* __restrict__ w2, const float* __restrict__ b2,
    const float* __restrict__ w3, const float* __restrict__ b3,
    const float* __restrict__ w4, const float* __restrict__ b4)
{
    __shared__ float s[W_TOTAL];
    for (int i = threadIdx.x; i < W_TOTAL; i += 256) {
        float v;
        if (i < OFF_B1)       v = w1[i - OFF_W1];
        else if (i < OFF_W2)  v = b1[i - OFF_B1];
        else if (i < OFF_B2)  v = w2[i - OFF_W2];
        else if (i < OFF_W3)  v = b2[i - OFF_B2];
        else if (i < OFF_B3)  v = w3[i - OFF_W3];
        else if (i < OFF_W4)  v = b3[i - OFF_B3];
        else if (i < OFF_B4)  v = w4[i - OFF_W4];
        else                  v = b4[0];
        s[i] = v;
    }
    __syncthreads();

    int m = blockIdx.x * 256 + threadIdx.x;
    if (m >= M_PTS) return;

    float x[7];
    #pragma unroll
    for (int f = 0; f < 7; ++f) x[f] = xin[f * M_PTS + m];

    float h1[18];
    #pragma unroll
    for (int o = 0; o < 18; ++o) {
        float a = s[OFF_B1 + o];
        #pragma unroll
        for (int i = 0; i < 7; ++i) a = fmaf(s[OFF_W1 + o * 7 + i], x[i], a);
        h1[o] = fmaxf(a, 0.0f);
    }

    float h2[36];
    #pragma unroll
    for (int o = 0; o < 36; ++o) {
        float a = s[OFF_B2 + o];
        #pragma unroll
        for (int i = 0; i < 18; ++i) a = fmaf(s[OFF_W2 + o * 18 + i], h1[i], a);
        h2[o] = fmaxf(a, 0.0f);
    }

    float h3[36];
    #pragma unroll
    for (int o = 0; o < 36; ++o) {
        float a = s[OFF_B3 + o];
        #pragma unroll
        for (int i = 0; i < 36; ++i) a = fmaf(s[OFF_W3 + o * 36 + i], h2[i], a);
        h3[o] = fmaxf(a, 0.0f);
    }

    float v = s[OFF_B4];
    #pragma unroll
    for (int i = 0; i < 36; ++i) v = fmaf(s[OFF_W4 + i], h3[i], v);

    int r = tind[m];
    int c = tind[M_PTS + m];
    unsigned long long key =
        (((unsigned long long)(unsigned)(m + 1)) << 32) |
        (unsigned long long)__float_as_uint(v);
    atomicMax(&g_cells[r * N_DIM + c], key);
}

__device__ __forceinline__ float cell_val(unsigned long long k) {
    return (k == 0ull) ? SENTINEL : __uint_as_float((unsigned)(k & 0xFFFFFFFFull));
}

__global__ void row_max_kernel(float* out) {
    int i = blockIdx.x;
    __shared__ float red[256];
    float mx = SENTINEL;
    for (int j = threadIdx.x; j < N_DIM; j += 256)
        mx = fmaxf(mx, cell_val(g_cells[i * N_DIM + j]));
    red[threadIdx.x] = mx;
    __syncthreads();
    #pragma unroll
    for (int s2 = 128; s2 > 0; s2 >>= 1) {
        if (threadIdx.x < s2)
            red[threadIdx.x] = fmaxf(red[threadIdx.x], red[threadIdx.x + s2]);
        __syncthreads();
    }
    if (threadIdx.x == 0) out[i] = red[0];
}

// Order-preserving float atomic max (handles mixed signs; accumulator init -inf).
__device__ __forceinline__ void atomicMaxFloat(float* addr, float val) {
    if (val >= 0.0f) atomicMax((int*)addr, __float_as_int(val));
    else             atomicMin((unsigned int*)addr, __float_as_uint(val));
}

// blockDim (64,4): 64 cols wide, 256-row strip per blockIdx.y. Coalesced reads.
__global__ void col_max_kernel(float* out) {
    int j = blockIdx.x * 64 + threadIdx.x;
    float mx = SENTINEL;
    if (j < N_DIM) {
        int r0 = blockIdx.y * 256;
        int r1 = min(r0 + 256, K_DIM);
        for (int r = r0 + threadIdx.y; r < r1; r += 4)
            mx = fmaxf(mx, cell_val(g_cells[r * N_DIM + j]));
    }
    __shared__ float red[4][64];
    red[threadIdx.y][threadIdx.x] = mx;
    __syncthreads();
    if (threadIdx.y == 0 && j < N_DIM) {
        float m2 = fmaxf(fmaxf(red[0][threadIdx.x], red[1][threadIdx.x]),
                         fmaxf(red[2][threadIdx.x], red[3][threadIdx.x]));
        atomicMaxFloat(&out[K_DIM + j], m2);
    }
}

extern "C" void kernel_launch(void* const* d_in, const int* in_sizes, int n_in,
                              void* d_out, int out_size) {
    const float* xin = (const float*)d_in[0];
    // d_in[1] = T_out (zeros, unused)
    const int*   tind = (const int*)d_in[2];
    const float* w1 = (const float*)d_in[3];
    const float* b1 = (const float*)d_in[4];
    const float* w2 = (const float*)d_in[5];
    const float* b2 = (const float*)d_in[6];
    const float* w3 = (const float*)d_in[7];
    const float* b3 = (const float*)d_in[8];
    const float* w4 = (const float*)d_in[9];
    const float* b4 = (const float*)d_in[10];
    float* out = (float*)d_out;

    init_kernel<<<(K_DIM * N_DIM + 255) / 256, 256>>>(out);
    mlp_scatter_kernel<<<(M_PTS + 255) / 256, 256>>>(
        xin, tind, w1, b1, w2, b2, w3, b3, w4, b4);
    row_max_kernel<<<K_DIM, 256>>>(out);
    dim3 cb(64, 4), cg(16, 4);
    col_max_kernel<<<cg, cb>>>(out);
}

// round 2
// speedup vs baseline: 1.0165x; 1.0165x over previous
#include <cuda_runtime.h>
#include <math.h>

#define K_DIM 1000
#define N_DIM 1000
#define M_PTS 900000
#define SENTINEL -9999.0f

typedef unsigned long long u64;

// Scratch grid: packed cells. High 32 bits = (m+1) (scatter order priority,
// last-write-wins like XLA in-order scatter), low 32 bits = float bits of val.
__device__ u64 g_cells[K_DIM * N_DIM];

__global__ void init_kernel(float* out) {
    int i = blockIdx.x * blockDim.x + threadIdx.x;
    if (i < K_DIM * N_DIM) g_cells[i] = 0ull;
    if (i < N_DIM) out[K_DIM + i] = -INFINITY;  // col_max accumulators
}

// Weight layout offsets (in weight-index units; shared holds float2 dups)
#define OFF_W1 0
#define OFF_B1 126
#define OFF_W2 144
#define OFF_B2 792
#define OFF_W3 828
#define OFF_B3 2124
#define OFF_W4 2160
#define OFF_B4 2196
#define W_TOTAL 2197

__device__ __forceinline__ u64 fma2(u64 a, u64 b, u64 c) {
    u64 d;
    asm("fma.rn.f32x2 %0, %1, %2, %3;" : "=l"(d) : "l"(a), "l"(b), "l"(c));
    return d;
}

__device__ __forceinline__ u64 relu2(u64 a) {
    u64 r;
    asm("{\n\t"
        ".reg .f32 l, h;\n\t"
        "mov.b64 {l, h}, %1;\n\t"
        "max.f32 l, l, 0f00000000;\n\t"
        "max.f32 h, h, 0f00000000;\n\t"
        "mov.b64 %0, {l, h};\n\t"
        "}" : "=l"(r) : "l"(a));
    return r;
}

__device__ __forceinline__ u64 mk64(unsigned lo, unsigned hi) {
    return ((u64)hi << 32) | (u64)lo;
}

__global__ __launch_bounds__(128) void mlp_scatter_kernel(
    const float* __restrict__ xin, const int* __restrict__ tind,
    const float* __restrict__ w1, const float* __restrict__ b1,
    const float* __restrict__ w2, const float* __restrict__ b2,
    const float* __restrict__ w3, const float* __restrict__ b3,
    const float* __restrict__ w4, const float* __restrict__ b4)
{
    // Each weight duplicated into both f32x2 lanes: s[i] = (w_i, w_i).
    __shared__ float2 s[W_TOTAL + 1];  // +1 pad keeps uint4 reads in-bounds
    for (int i = threadIdx.x; i < W_TOTAL; i += 128) {
        float v;
        if (i < OFF_B1)       v = w1[i - OFF_W1];
        else if (i < OFF_W2)  v = b1[i - OFF_B1];
        else if (i < OFF_B2)  v = w2[i - OFF_W2];
        else if (i < OFF_W3)  v = b2[i - OFF_B2];
        else if (i < OFF_B3)  v = w3[i - OFF_W3];
        else if (i < OFF_W4)  v = b3[i - OFF_B3];
        else if (i < OFF_B4)  v = w4[i - OFF_W4];
        else                  v = b4[0];
        s[i] = make_float2(v, v);
    }
    if (threadIdx.x == 0) s[W_TOTAL] = make_float2(0.f, 0.f);
    __syncthreads();

    int p = blockIdx.x * 128 + threadIdx.x;
    int m0 = 2 * p;
    if (m0 >= M_PTS) return;

    const u64* sv = reinterpret_cast<const u64*>(s);

    // Load 2 points' inputs as packed pairs (m-contiguous, 8B aligned: m0 even).
    u64 x[7];
    #pragma unroll
    for (int f = 0; f < 7; ++f)
        x[f] = *reinterpret_cast<const u64*>(&xin[f * M_PTS + m0]);

    // Layer 1: 7 -> 18 (row length odd: plain 64-bit weight loads)
    u64 h1[18];
    #pragma unroll
    for (int o = 0; o < 18; ++o) {
        u64 a = sv[OFF_B1 + o];
        #pragma unroll
        for (int i = 0; i < 7; ++i)
            a = fma2(sv[OFF_W1 + o * 7 + i], x[i], a);
        h1[o] = relu2(a);
    }

    // Layer 2: 18 -> 36 (uint4 = 2 duplicated weights per LDS.128)
    u64 h2[36];
    #pragma unroll
    for (int o = 0; o < 36; ++o) {
        u64 a = sv[OFF_B2 + o];
        #pragma unroll
        for (int i = 0; i < 18; i += 2) {
            uint4 q = *reinterpret_cast<const uint4*>(&s[OFF_W2 + o * 18 + i]);
            a = fma2(mk64(q.x, q.y), h1[i], a);
            a = fma2(mk64(q.z, q.w), h1[i + 1], a);
        }
        h2[o] = relu2(a);
    }

    // Layer 3: 36 -> 36
    u64 h3[36];
    #pragma unroll
    for (int o = 0; o < 36; ++o) {
        u64 a = sv[OFF_B3 + o];
        #pragma unroll
        for (int i = 0; i < 36; i += 2) {
            uint4 q = *reinterpret_cast<const uint4*>(&s[OFF_W3 + o * 36 + i]);
            a = fma2(mk64(q.x, q.y), h2[i], a);
            a = fma2(mk64(q.z, q.w), h2[i + 1], a);
        }
        h3[o] = relu2(a);
    }

    // Layer 4: 36 -> 1
    u64 v = sv[OFF_B4];
    #pragma unroll
    for (int i = 0; i < 36; i += 2) {
        uint4 q = *reinterpret_cast<const uint4*>(&s[OFF_W4 + i]);
        v = fma2(mk64(q.x, q.y), h3[i], v);
        v = fma2(mk64(q.z, q.w), h3[i + 1], v);
    }

    unsigned v0 = (unsigned)(v & 0xFFFFFFFFull);
    unsigned v1 = (unsigned)(v >> 32);

    int2 rr = *reinterpret_cast<const int2*>(&tind[m0]);
    int2 cc = *reinterpret_cast<const int2*>(&tind[M_PTS + m0]);

    u64 key0 = (((u64)(unsigned)(m0 + 1)) << 32) | (u64)v0;
    u64 key1 = (((u64)(unsigned)(m0 + 2)) << 32) | (u64)v1;
    atomicMax(&g_cells[rr.x * N_DIM + cc.x], key0);
    atomicMax(&g_cells[rr.y * N_DIM + cc.y], key1);
}

__device__ __forceinline__ float cell_val(u64 k) {
    return (k == 0ull) ? SENTINEL : __uint_as_float((unsigned)(k & 0xFFFFFFFFull));
}

__global__ void row_max_kernel(float* out) {
    int i = blockIdx.x;
    __shared__ float red[256];
    float mx = SENTINEL;
    for (int j = threadIdx.x; j < N_DIM; j += 256)
        mx = fmaxf(mx, cell_val(g_cells[i * N_DIM + j]));
    red[threadIdx.x] = mx;
    __syncthreads();
    #pragma unroll
    for (int s2 = 128; s2 > 0; s2 >>= 1) {
        if (threadIdx.x < s2)
            red[threadIdx.x] = fmaxf(red[threadIdx.x], red[threadIdx.x + s2]);
        __syncthreads();
    }
    if (threadIdx.x == 0) out[i] = red[0];
}

// Order-preserving float atomic max (mixed signs; accumulator init -inf).
__device__ __forceinline__ void atomicMaxFloat(float* addr, float val) {
    if (val >= 0.0f) atomicMax((int*)addr, __float_as_int(val));
    else             atomicMin((unsigned int*)addr, __float_as_uint(val));
}

// blockDim (64,4): 64 cols wide, 64-row strip per blockIdx.y -> 256 blocks.
__global__ void col_max_kernel(float* out) {
    int j = blockIdx.x * 64 + threadIdx.x;
    float mx = SENTINEL;
    if (j < N_DIM) {
        int r0 = blockIdx.y * 64;
        int r1 = min(r0 + 64, K_DIM);
        for (int r = r0 + threadIdx.y; r < r1; r += 4)
            mx = fmaxf(mx, cell_val(g_cells[r * N_DIM + j]));
    }
    __shared__ float red[4][64];
    red[threadIdx.y][threadIdx.x] = mx;
    __syncthreads();
    if (threadIdx.y == 0 && j < N_DIM) {
        float m2 = fmaxf(fmaxf(red[0][threadIdx.x], red[1][threadIdx.x]),
                         fmaxf(red[2][threadIdx.x], red[3][threadIdx.x]));
        atomicMaxFloat(&out[K_DIM + j], m2);
    }
}

extern "C" void kernel_launch(void* const* d_in, const int* in_sizes, int n_in,
                              void* d_out, int out_size) {
    const float* xin = (const float*)d_in[0];
    // d_in[1] = T_out (zeros, unused)
    const int*   tind = (const int*)d_in[2];
    const float* w1 = (const float*)d_in[3];
    const float* b1 = (const float*)d_in[4];
    const float* w2 = (const float*)d_in[5];
    const float* b2 = (const float*)d_in[6];
    const float* w3 = (const float*)d_in[7];
    const float* b3 = (const float*)d_in[8];
    const float* w4 = (const float*)d_in[9];
    const float* b4 = (const float*)d_in[10];
    float* out = (float*)d_out;

    init_kernel<<<(K_DIM * N_DIM + 255) / 256, 256>>>(out);
    int pairs = M_PTS / 2;
    mlp_scatter_kernel<<<(pairs + 127) / 128, 128>>>(
        xin, tind, w1, b1, w2, b2, w3, b3, w4, b4);
    row_max_kernel<<<K_DIM, 256>>>(out);
    dim3 cb(64, 4), cg(16, 16);
    col_max_kernel<<<cg, cb>>>(out);
}